// round 11
// baseline (speedup 1.0000x reference)
#include <cuda_runtime.h>
#include <cuda_fp16.h>
#include <cstdint>

#define DEV_INLINE __device__ __forceinline__

static constexpr int NDIM   = 1024;
static constexpr int NBATCH = 32;

// GEMM tiling (portable mma.sync; tcgen05 rejected by compute_103 PTX target)
static constexpr int BM = 128;
static constexpr int BN = 128;
static constexpr int BK = 64;         // 64 fp16 = 128 B
static constexpr int STAGES = 3;
static constexpr int THREADS = 256;   // 8 warps: 2(m) x 4(n), warp tile 64x32 (proven config)

static constexpr int A_STAGE_BYTES = BM * 128;              // 16 KB
static constexpr int STAGE_BYTES   = 2 * A_STAGE_BYTES;     // 32 KB
static constexpr int SMEM_TOTAL    = STAGES * STAGE_BYTES;  // 96 KB

// Folded DCT (level 2 on the even branch):
//   odd rows  k=2r+1: Out = Codd(512x512) @ d    d[j]  = x[j]-x[1023-j]           (j<512)
//   rows k=4t:        Out = Cee (256x256) @ ss   ss[j] = s[j]+s[511-j]            (j<256)
//   rows k=4t+2:      Out = Ceo (256x256) @ sd   sd[j] = s[j]-s[511-j]
//   with s[j] = x[j]+x[1023-j]
__device__ __half d_Codd[512 * 512];
__device__ __half d_Cee[256 * 256];
__device__ __half d_Ceo[256 * 256];
__device__ __half d_xd [(size_t)NBATCH * 1024 * 512];   // [b][m][j<512]  (K-contig)
__device__ __half d_xss[(size_t)NBATCH * 1024 * 256];   // [b][m][j<256]
__device__ __half d_xsd[(size_t)NBATCH * 1024 * 256];

// ---------------------------------------------------------------- helpers
DEV_INLINE uint32_t smem_u32(const void* p) {
    uint32_t a;
    asm("{ .reg .u64 t; cvta.to.shared.u64 t, %1; cvt.u32.u64 %0, t; }" : "=r"(a) : "l"(p));
    return a;
}
DEV_INLINE void cp16(uint32_t saddr, const void* g) {
    asm volatile("cp.async.cg.shared.global [%0], [%1], 16;" :: "r"(saddr), "l"(g));
}
DEV_INLINE void cp_commit() { asm volatile("cp.async.commit_group;"); }
template <int N> DEV_INLINE void cp_wait() { asm volatile("cp.async.wait_group %0;" :: "n"(N)); }
DEV_INLINE uint32_t swz(uint32_t off) { return off ^ ((off >> 3) & 0x70); }

DEV_INLINE void ldsm4(uint32_t* r, uint32_t addr) {
    asm volatile("ldmatrix.sync.aligned.m8n8.x4.shared.b16 {%0,%1,%2,%3}, [%4];"
                 : "=r"(r[0]), "=r"(r[1]), "=r"(r[2]), "=r"(r[3]) : "r"(addr));
}
DEV_INLINE void mma16816(float* c, const uint32_t* a, const uint32_t* b) {
    asm volatile(
        "mma.sync.aligned.m16n8k16.row.col.f32.f16.f16.f32 "
        "{%0,%1,%2,%3}, {%4,%5,%6,%7}, {%8,%9}, {%0,%1,%2,%3};"
        : "+f"(c[0]), "+f"(c[1]), "+f"(c[2]), "+f"(c[3])
        : "r"(a[0]), "r"(a[1]), "r"(a[2]), "r"(a[3]), "r"(b[0]), "r"(b[1]));
}

// ---------------------------------------------------------------- kernel 1: DCT matrices
// entry = scale(k) * cos(pi * ((2j+1)k mod 4096) / 2048)
__global__ void build_c_kernel() {
    int idx = blockIdx.x * 256 + threadIdx.x;   // 0 .. 393215
    int k, j;
    __half* dst;
    if (idx < 262144) {                         // Codd: r<512, j<512, k=2r+1
        j = idx & 511; k = 2 * (idx >> 9) + 1; dst = d_Codd + idx;
    } else if (idx < 327680) {                  // Cee: t<256, j<256, k=4t
        int l = idx - 262144;
        j = l & 255; k = 4 * (l >> 8); dst = d_Cee + l;
    } else {                                    // Ceo: k=4t+2
        int l = idx - 327680;
        j = l & 255; k = 4 * (l >> 8) + 2; dst = d_Ceo + l;
    }
    int t = ((k * (2 * j + 1) + 2048) & 4095) - 2048;   // angle -> [-pi, pi)
    float ang = (float)t * 1.5339807878856412e-3f;      // pi/2048
    float s = (k == 0) ? 0.03125f : 0.04419417382415922f;
    *dst = __float2half(s * __cosf(ang));
}

// ---------------------------------------------------------------- kernel 2: fold + transpose
// Block handles m-tile (32) x jj-tile (64), jj<256. Reads x row-groups jj, 1023-jj,
// 511-jj, 512+jj; writes d (rows jj and 511-jj), ss, sd in [b][m][j] K-contig layout.
__global__ void fold_kernel(const float* __restrict__ x) {
    __shared__ float tA[64][33], tB[64][33], tC[64][33], tD[64][33];
    int b = blockIdx.z;
    int m0 = blockIdx.x * 32, jj0 = blockIdx.y * 64;    // jj0 in {0,64,128,192}
    const float* xb = x + ((size_t)b << 20);
    int tx = threadIdx.x, ty = threadIdx.y;
#pragma unroll
    for (int r = ty; r < 64; r += 8) {
        tA[r][tx] = xb[(size_t)(jj0 + r) * 1024 + m0 + tx];
        tB[r][tx] = xb[(size_t)(1023 - jj0 - r) * 1024 + m0 + tx];
        tC[r][tx] = xb[(size_t)(511 - jj0 - r) * 1024 + m0 + tx];
        tD[r][tx] = xb[(size_t)(512 + jj0 + r) * 1024 + m0 + tx];
    }
    __syncthreads();
    int jd0 = 448 - jj0;                        // d[511-jj] lands in [jd0, jd0+64)
    __half2* xd2  = (__half2*)d_xd;
    __half2* xss2 = (__half2*)d_xss;
    __half2* xsd2 = (__half2*)d_xsd;
#pragma unroll
    for (int r = ty; r < 32; r += 8) {          // r = m-row within tile; tx = j-pair
        size_t rowd = ((size_t)b * 1024 + m0 + r) * 256;   // d_xd row in half2 units
        size_t rows = ((size_t)b * 1024 + m0 + r) * 128;   // ss/sd row in half2 units
        float a0 = tA[2 * tx][r],     b0 = tB[2 * tx][r];
        float a1 = tA[2 * tx + 1][r], b1 = tB[2 * tx + 1][r];
        float c0 = tC[2 * tx][r],     e0 = tD[2 * tx][r];
        float c1 = tC[2 * tx + 1][r], e1 = tD[2 * tx + 1][r];
        // d[jj] = x[jj]-x[1023-jj]
        xd2[rowd + (jj0 >> 1) + tx] = __floats2half2_rn(a0 - b0, a1 - b1);
        // d[511-jj] = x[511-jj]-x[512+jj], reversed within tile (rr = 63-2tx, 62-2tx)
        float ch0 = tC[63 - 2 * tx][r], eh0 = tD[63 - 2 * tx][r];
        float ch1 = tC[62 - 2 * tx][r], eh1 = tD[62 - 2 * tx][r];
        xd2[rowd + (jd0 >> 1) + tx] = __floats2half2_rn(ch0 - eh0, ch1 - eh1);
        // ss/sd: s[jj] = a+b, s[511-jj] = c+e
        float slo0 = a0 + b0, shi0 = c0 + e0;
        float slo1 = a1 + b1, shi1 = c1 + e1;
        xss2[rows + (jj0 >> 1) + tx] = __floats2half2_rn(slo0 + shi0, slo1 + shi1);
        xsd2[rows + (jj0 >> 1) + tx] = __floats2half2_rn(slo0 - shi0, slo1 - shi1);
    }
}

// ---------------------------------------------------------------- kernel 3: fused GEMM
// Out[ROWMUL*(k0+rr)+ROWOFF, n] = sum_{j<KD} A[k0+rr, j] * B[n, j]   (n = b*1024+m)
template <int KD>
DEV_INLINE void load_chunk(int q, int stage, int tid, const __half* Asrc,
                           const __half* Bsrc, uint32_t sbase) {
    uint32_t abase = sbase + stage * STAGE_BYTES;
    uint32_t bbase = abase + A_STAGE_BYTES;
    int kc0 = q * BK;
#pragma unroll
    for (int i = 0; i < 4; i++) {
        int s = tid + i * THREADS;
        int row = s >> 3, seg = s & 7;
        cp16(abase + swz((uint32_t)(row * 128 + seg * 16)),
             (const void*)(Asrc + (size_t)row * KD + kc0 + seg * 8));
    }
#pragma unroll
    for (int i = 0; i < 4; i++) {
        int s = tid + i * THREADS;
        int row = s >> 3, seg = s & 7;
        cp16(bbase + swz((uint32_t)(row * 128 + seg * 16)),
             (const void*)(Bsrc + (size_t)row * KD + kc0 + seg * 8));
    }
}

template <int KD, int SEL, int ROWMUL, int ROWOFF>
DEV_INLINE void gemm_body(float* __restrict__ out, int kt, int nt, uint32_t sbase,
                          char* smem) {
    constexpr int NCH = KD / BK;
    int tid = threadIdx.x;
    int lane = tid & 31, wid = tid >> 5;
    int warp_m = wid & 1;          // 2 m-warps (64 rows)
    int warp_n = wid >> 1;         // 4 n-warps (32 cols)

    const __half* Amat = (SEL == 0) ? d_Codd : (SEL == 1) ? d_Cee : d_Ceo;
    const __half* Bmat = (SEL == 0) ? d_xd   : (SEL == 1) ? d_xss : d_xsd;

    int k0 = kt * BM;
    int b  = nt >> 3;
    int m0 = (nt & 7) * BN;
    const __half* Apanel = Amat + (size_t)k0 * KD;
    const __half* Bpanel = Bmat + ((size_t)b * 1024 + m0) * KD;

    float acc[4][4][4] = {};

    // ldmatrix address components (proven mapping, both operands non-trans)
    int a_row = warp_m * 64 + (lane & 7) + (((lane >> 3) & 1) << 3);
    int a_kx  = (lane >> 4) << 3;
    int b_row = warp_n * 32 + (lane & 7) + ((lane >> 4) << 3);
    int b_kx  = ((lane >> 3) & 1) << 3;

#pragma unroll
    for (int s = 0; s < STAGES - 1; s++) {
        load_chunk<KD>(s, s, tid, Apanel, Bpanel, sbase); cp_commit();
    }

    for (int c = 0; c < NCH; c++) {
        int q = c + STAGES - 1;
        if (q < NCH) load_chunk<KD>(q, q % STAGES, tid, Apanel, Bpanel, sbase);
        cp_commit();
        cp_wait<STAGES - 1>();
        __syncthreads();

        uint32_t abase = sbase + (c % STAGES) * STAGE_BYTES;
        uint32_t bbase = abase + A_STAGE_BYTES;
#pragma unroll
        for (int ks = 0; ks < BK / 16; ks++) {
            uint32_t af[4][4];
#pragma unroll
            for (int mi = 0; mi < 4; mi++)
                ldsm4(af[mi], abase + swz((uint32_t)((a_row + mi * 16) * 128 +
                                                     (ks * 16 + a_kx) * 2)));
            uint32_t bf[4][2];
#pragma unroll
            for (int h = 0; h < 2; h++) {
                uint32_t r[4];
                ldsm4(r, bbase + swz((uint32_t)((b_row + h * 16) * 128 +
                                                (ks * 16 + b_kx) * 2)));
                bf[2 * h + 0][0] = r[0]; bf[2 * h + 0][1] = r[1];
                bf[2 * h + 1][0] = r[2]; bf[2 * h + 1][1] = r[3];
            }
#pragma unroll
            for (int mi = 0; mi < 4; mi++)
#pragma unroll
                for (int ni = 0; ni < 4; ni++)
                    mma16816(acc[mi][ni], af[mi], bf[ni]);
        }
        __syncthreads();
    }

    // epilogue: regs -> smem (stride 132) -> float4 stores, output row stride ROWMUL*1024
    float* stg = (float*)smem;
    int gr = lane >> 2, cl = (lane & 3) * 2;
#pragma unroll
    for (int mi = 0; mi < 4; mi++)
#pragma unroll
        for (int ni = 0; ni < 4; ni++) {
            int r0 = warp_m * 64 + mi * 16 + gr;
            int col = warp_n * 32 + ni * 8 + cl;
            stg[r0 * 132 + col]           = acc[mi][ni][0];
            stg[r0 * 132 + col + 1]       = acc[mi][ni][1];
            stg[(r0 + 8) * 132 + col]     = acc[mi][ni][2];
            stg[(r0 + 8) * 132 + col + 1] = acc[mi][ni][3];
        }
    __syncthreads();

    size_t ob = ((size_t)b << 20) + (size_t)(ROWMUL * k0 + ROWOFF) * 1024 + m0;
    constexpr size_t rstride = (size_t)ROWMUL * 1024;
#pragma unroll
    for (int i = 0; i < 16; i++) {
        int idx = i * THREADS + tid;         // 4096 float4s = 128 rows x 32
        int row = idx >> 5;
        int c4 = (idx & 31) * 4;
        float4 v = *(const float4*)(stg + row * 132 + c4);
        *(float4*)(out + ob + (size_t)row * rstride + c4) = v;
    }
}

// One launch for all 3 GEMM segments: 1024 (odd) + 512 (ee) + 512 (eo) = 2048 CTAs.
// kt varies fastest so consecutive CTAs share the B panel (L2 reuse).
__global__ void __launch_bounds__(THREADS, 2) fused_gemm_kernel(float* __restrict__ out) {
    extern __shared__ char smem[];
    uint32_t sbase = smem_u32(smem);
    int blk = blockIdx.x;
    if (blk < 1024) {
        gemm_body<512, 0, 2, 1>(out, blk & 3, blk >> 2, sbase, smem);
    } else if (blk < 1536) {
        int l = blk - 1024;
        gemm_body<256, 1, 4, 0>(out, l & 1, l >> 1, sbase, smem);
    } else {
        int l = blk - 1536;
        gemm_body<256, 2, 4, 2>(out, l & 1, l >> 1, sbase, smem);
    }
}

// ---------------------------------------------------------------- launch
extern "C" void kernel_launch(void* const* d_in, const int* in_sizes, int n_in,
                              void* d_out, int out_size) {
    (void)in_sizes; (void)n_in; (void)out_size;
    const float* x = (const float*)d_in[0];
    float* out = (float*)d_out;

    build_c_kernel<<<1536, 256>>>();

    dim3 fg(32, 4, NBATCH), fb(32, 8);
    fold_kernel<<<fg, fb>>>(x);

    cudaFuncSetAttribute(fused_gemm_kernel,
                         cudaFuncAttributeMaxDynamicSharedMemorySize, SMEM_TOTAL);
    fused_gemm_kernel<<<2048, THREADS, SMEM_TOTAL>>>(out);
}

// round 12
// speedup vs baseline: 1.1552x; 1.1552x over previous
#include <cuda_runtime.h>
#include <cuda_fp16.h>
#include <cstdint>

#define DEV_INLINE __device__ __forceinline__

static constexpr int NDIM   = 1024;
static constexpr int NBATCH = 32;

// GEMM tiling (portable mma.sync; tcgen05 rejected by compute_103 PTX target)
static constexpr int BM = 128;
static constexpr int BN = 128;
static constexpr int BK = 64;         // K per chunk
static constexpr int STAGES = 3;
static constexpr int THREADS = 256;   // 8 warps: 2(m) x 4(n), warp tile 64x32 (proven config)

static constexpr int A_STAGE_BYTES = BM * 128;              // 16 KB (128 rows x 128B)
static constexpr int B_STAGE_BYTES = BK * 256;              // 16 KB (64 k-rows x 128 m x fp16)
static constexpr int STAGE_BYTES   = A_STAGE_BYTES + B_STAGE_BYTES;   // 32 KB
static constexpr int SMEM_TOTAL    = STAGES * STAGE_BYTES;  // 96 KB

// Folded DCT (level 2 on the even branch), B operands kept in INPUT layout [b][j][m]:
//   odd rows  k=2r+1: Out = Codd(512x512) @ d    d[j][m]  = x[j][m]-x[1023-j][m]   (j<512)
//   rows k=4t:        Out = Cee (256x256) @ ss   ss[j][m] = s[j]+s[511-j]          (j<256)
//   rows k=4t+2:      Out = Ceo (256x256) @ sd   sd[j][m] = s[j]-s[511-j]
//   with s[j] = x[j]+x[1023-j]
__device__ __half d_Codd[512 * 512];                    // [r][j] K-contig
__device__ __half d_Cee[256 * 256];
__device__ __half d_Ceo[256 * 256];
__device__ __half d_xd [(size_t)NBATCH * 512 * 1024];   // [b][j<512][m]
__device__ __half d_xss[(size_t)NBATCH * 256 * 1024];   // [b][j<256][m]
__device__ __half d_xsd[(size_t)NBATCH * 256 * 1024];

// ---------------------------------------------------------------- helpers
DEV_INLINE uint32_t smem_u32(const void* p) {
    uint32_t a;
    asm("{ .reg .u64 t; cvta.to.shared.u64 t, %1; cvt.u32.u64 %0, t; }" : "=r"(a) : "l"(p));
    return a;
}
DEV_INLINE void cp16(uint32_t saddr, const void* g) {
    asm volatile("cp.async.cg.shared.global [%0], [%1], 16;" :: "r"(saddr), "l"(g));
}
DEV_INLINE void cp_commit() { asm volatile("cp.async.commit_group;"); }
template <int N> DEV_INLINE void cp_wait() { asm volatile("cp.async.wait_group %0;" :: "n"(N)); }
DEV_INLINE uint32_t swz(uint32_t off) { return off ^ ((off >> 3) & 0x70); }

DEV_INLINE void ldsm4(uint32_t* r, uint32_t addr) {
    asm volatile("ldmatrix.sync.aligned.m8n8.x4.shared.b16 {%0,%1,%2,%3}, [%4];"
                 : "=r"(r[0]), "=r"(r[1]), "=r"(r[2]), "=r"(r[3]) : "r"(addr));
}
DEV_INLINE void ldsm4t(uint32_t* r, uint32_t addr) {
    asm volatile("ldmatrix.sync.aligned.m8n8.x4.trans.shared.b16 {%0,%1,%2,%3}, [%4];"
                 : "=r"(r[0]), "=r"(r[1]), "=r"(r[2]), "=r"(r[3]) : "r"(addr));
}
DEV_INLINE void mma16816(float* c, const uint32_t* a, const uint32_t* b) {
    asm volatile(
        "mma.sync.aligned.m16n8k16.row.col.f32.f16.f16.f32 "
        "{%0,%1,%2,%3}, {%4,%5,%6,%7}, {%8,%9}, {%0,%1,%2,%3};"
        : "+f"(c[0]), "+f"(c[1]), "+f"(c[2]), "+f"(c[3])
        : "r"(a[0]), "r"(a[1]), "r"(a[2]), "r"(a[3]), "r"(b[0]), "r"(b[1]));
}
DEV_INLINE uint32_t f2h2(float a, float b) {
    __half2 h = __floats2half2_rn(a, b);
    return *reinterpret_cast<uint32_t*>(&h);
}
DEV_INLINE float4 add4(float4 a, float4 b) { return {a.x+b.x, a.y+b.y, a.z+b.z, a.w+b.w}; }
DEV_INLINE float4 sub4(float4 a, float4 b) { return {a.x-b.x, a.y-b.y, a.z-b.z, a.w-b.w}; }
DEV_INLINE void st8h(__half* p, float4 u, float4 v) {
    uint4 o = { f2h2(u.x,u.y), f2h2(u.z,u.w), f2h2(v.x,v.y), f2h2(v.z,v.w) };
    *reinterpret_cast<uint4*>(p) = o;
}

// ---------------------------------------------------------------- kernel 1: DCT matrices
// entry = scale(k) * cos(pi * ((2j+1)k mod 4096) / 2048)
__global__ void build_c_kernel() {
    int idx = blockIdx.x * 256 + threadIdx.x;   // 0 .. 393215
    int k, j;
    __half* dst;
    if (idx < 262144) {                         // Codd: r<512, j<512, k=2r+1
        j = idx & 511; k = 2 * (idx >> 9) + 1; dst = d_Codd + idx;
    } else if (idx < 327680) {                  // Cee: t<256, j<256, k=4t
        int l = idx - 262144;
        j = l & 255; k = 4 * (l >> 8); dst = d_Cee + l;
    } else {                                    // Ceo: k=4t+2
        int l = idx - 327680;
        j = l & 255; k = 4 * (l >> 8) + 2; dst = d_Ceo + l;
    }
    int t = ((k * (2 * j + 1) + 2048) & 4095) - 2048;   // angle -> [-pi, pi)
    float ang = (float)t * 1.5339807878856412e-3f;      // pi/2048
    float s = (k == 0) ? 0.03125f : 0.04419417382415922f;
    *dst = __float2half(s * __cosf(ang));
}

// ---------------------------------------------------------------- kernel 2: streaming fold
// NO transpose: outputs stay in [b][j][m] layout. Each thread handles one
// (b, j<256, 8-m group): reads 4 x-rows, writes d[j], d[511-j], ss[j], sd[j].
// Every access a full coalesced transaction; each x row read exactly once.
__global__ void fold_kernel(const float* __restrict__ x) {
    int idx = blockIdx.x * 256 + threadIdx.x;   // 0 .. 1048575
    int b = idx >> 15;
    int rem = idx & 32767;
    int j = rem >> 7;                            // 0..255
    int m = (rem & 127) << 3;                    // 8 floats
    const float* xb = x + ((size_t)b << 20);
    const float4* pa = (const float4*)(xb + (size_t)j * 1024 + m);
    const float4* pb = (const float4*)(xb + (size_t)(1023 - j) * 1024 + m);
    const float4* pc = (const float4*)(xb + (size_t)(511 - j) * 1024 + m);
    const float4* pe = (const float4*)(xb + (size_t)(512 + j) * 1024 + m);
    float4 a0 = pa[0], a1 = pa[1];
    float4 b0 = pb[0], b1 = pb[1];
    float4 c0 = pc[0], c1 = pc[1];
    float4 e0 = pe[0], e1 = pe[1];

    float4 slo0 = add4(a0, b0), slo1 = add4(a1, b1);   // s[j]
    float4 shi0 = add4(c0, e0), shi1 = add4(c1, e1);   // s[511-j]

    st8h(d_xd  + ((size_t)b * 512 + j)       * 1024 + m, sub4(a0, b0), sub4(a1, b1));
    st8h(d_xd  + ((size_t)b * 512 + 511 - j) * 1024 + m, sub4(c0, e0), sub4(c1, e1));
    st8h(d_xss + ((size_t)b * 256 + j)       * 1024 + m, add4(slo0, shi0), add4(slo1, shi1));
    st8h(d_xsd + ((size_t)b * 256 + j)       * 1024 + m, sub4(slo0, shi0), sub4(slo1, shi1));
}

// ---------------------------------------------------------------- kernel 3: GEMM
// Out[ROWMUL*(k0+rr)+ROWOFF, n] = sum_{j<KD} A[k0+rr, j] * B[j, n]   (n = b*1024+m)
// A: [rows][KD] K-contig (non-trans ldsm). B: [b][KD][1024] -> trans ldsm.
template <int KD>
DEV_INLINE void load_chunk(int q, int stage, int tid, const __half* Asrc,
                           const __half* Bsrc, uint32_t sbase) {
    uint32_t abase = sbase + stage * STAGE_BYTES;
    uint32_t bbase = abase + A_STAGE_BYTES;
    int kc0 = q * BK;
    // A: 128 rows x 8 segs of 16B = 1024 segs
#pragma unroll
    for (int i = 0; i < 4; i++) {
        int s = tid + i * THREADS;
        int row = s >> 3, seg = s & 7;
        cp16(abase + swz((uint32_t)(row * 128 + seg * 16)),
             (const void*)(Asrc + (size_t)row * KD + kc0 + seg * 8));
    }
    // B: 64 k-rows x 16 segs of 16B (128 m), stored as two 8KB halves of 64 m-cols
#pragma unroll
    for (int i = 0; i < 4; i++) {
        int s = tid + i * THREADS;
        int krow = s >> 4, seg = s & 15;
        cp16(bbase + (uint32_t)((seg >> 3) * 8192) +
                 swz((uint32_t)(krow * 128 + (seg & 7) * 16)),
             (const void*)(Bsrc + (size_t)(kc0 + krow) * 1024 + seg * 8));
    }
}

template <int KD, int SEL, int ROWMUL, int ROWOFF>
__global__ void __launch_bounds__(THREADS, 2) gemm_kernel(float* __restrict__ out) {
    constexpr int NCH = KD / BK;
    extern __shared__ char smem[];
    uint32_t sbase = smem_u32(smem);
    int tid = threadIdx.x;
    int lane = tid & 31, wid = tid >> 5;
    int warp_m = wid & 1;          // 2 m-warps (64 rows)
    int warp_n = wid >> 1;         // 4 n-warps (32 cols)

    // device-side operand selection (host cannot pass __device__ symbols)
    const __half* Amat = (SEL == 0) ? d_Codd : (SEL == 1) ? d_Cee : d_Ceo;
    const __half* Bmat = (SEL == 0) ? d_xd   : (SEL == 1) ? d_xss : d_xsd;

    int k0 = blockIdx.x * BM;
    int b  = blockIdx.y >> 3;
    int m0 = (blockIdx.y & 7) * BN;
    const __half* Apanel = Amat + (size_t)k0 * KD;
    const __half* Bpanel = Bmat + (size_t)b * KD * 1024 + m0;

    float acc[4][4][4] = {};

    // A frag addresses (proven non-trans mapping)
    int a_row = warp_m * 64 + (lane & 7) + (((lane >> 3) & 1) << 3);
    int a_kx  = (lane >> 4) << 3;
    // B frag addresses (trans mapping): tiles (k0,n0),(k8,n0),(k0,n8),(k8,n8)
    int b_jr  = (lane & 7) + (((lane >> 3) & 1) << 3);   // k row within 16
    int b_ns  = (lane >> 4) << 3;                        // n +0 / +8

#pragma unroll
    for (int s = 0; s < STAGES - 1; s++) {
        load_chunk<KD>(s, s, tid, Apanel, Bpanel, sbase); cp_commit();
    }

    for (int c = 0; c < NCH; c++) {
        int q = c + STAGES - 1;
        if (q < NCH) load_chunk<KD>(q, q % STAGES, tid, Apanel, Bpanel, sbase);
        cp_commit();
        cp_wait<STAGES - 1>();
        __syncthreads();

        uint32_t abase = sbase + (c % STAGES) * STAGE_BYTES;
        uint32_t bbase = abase + A_STAGE_BYTES;
#pragma unroll
        for (int ks = 0; ks < BK / 16; ks++) {
            uint32_t af[4][4];
#pragma unroll
            for (int mi = 0; mi < 4; mi++)
                ldsm4(af[mi], abase + swz((uint32_t)((a_row + mi * 16) * 128 +
                                                     (ks * 16 + a_kx) * 2)));
            uint32_t bf[4][2];
#pragma unroll
            for (int g = 0; g < 2; g++) {        // 16 n per trans-ldsm4
                int nb = warp_n * 32 + g * 16 + b_ns;
                uint32_t r[4];
                ldsm4t(r, bbase + (uint32_t)(((nb >> 6) & 1) * 8192) +
                          swz((uint32_t)((ks * 16 + b_jr) * 128 + (nb & 63) * 2)));
                bf[2 * g + 0][0] = r[0]; bf[2 * g + 0][1] = r[1];
                bf[2 * g + 1][0] = r[2]; bf[2 * g + 1][1] = r[3];
            }
#pragma unroll
            for (int mi = 0; mi < 4; mi++)
#pragma unroll
                for (int ni = 0; ni < 4; ni++)
                    mma16816(acc[mi][ni], af[mi], bf[ni]);
        }
        __syncthreads();
    }

    // epilogue: regs -> smem (stride 132) -> float4 stores, output row stride ROWMUL*1024
    float* stg = (float*)smem;
    int gr = lane >> 2, cl = (lane & 3) * 2;
#pragma unroll
    for (int mi = 0; mi < 4; mi++)
#pragma unroll
        for (int ni = 0; ni < 4; ni++) {
            int r0 = warp_m * 64 + mi * 16 + gr;
            int col = warp_n * 32 + ni * 8 + cl;
            stg[r0 * 132 + col]           = acc[mi][ni][0];
            stg[r0 * 132 + col + 1]       = acc[mi][ni][1];
            stg[(r0 + 8) * 132 + col]     = acc[mi][ni][2];
            stg[(r0 + 8) * 132 + col + 1] = acc[mi][ni][3];
        }
    __syncthreads();

    size_t ob = ((size_t)b << 20) + (size_t)(ROWMUL * k0 + ROWOFF) * 1024 + m0;
    constexpr size_t rstride = (size_t)ROWMUL * 1024;
#pragma unroll
    for (int i = 0; i < 16; i++) {
        int idx = i * THREADS + tid;         // 4096 float4s = 128 rows x 32
        int row = idx >> 5;
        int c4 = (idx & 31) * 4;
        float4 v = *(const float4*)(stg + row * 132 + c4);
        *(float4*)(out + ob + (size_t)row * rstride + c4) = v;
    }
}

// ---------------------------------------------------------------- launch
extern "C" void kernel_launch(void* const* d_in, const int* in_sizes, int n_in,
                              void* d_out, int out_size) {
    (void)in_sizes; (void)n_in; (void)out_size;
    const float* x = (const float*)d_in[0];
    float* out = (float*)d_out;

    build_c_kernel<<<1536, 256>>>();
    fold_kernel<<<4096, 256>>>(x);

    cudaFuncSetAttribute(gemm_kernel<512, 0, 2, 1>,
                         cudaFuncAttributeMaxDynamicSharedMemorySize, SMEM_TOTAL);
    cudaFuncSetAttribute(gemm_kernel<256, 1, 4, 0>,
                         cudaFuncAttributeMaxDynamicSharedMemorySize, SMEM_TOTAL);
    cudaFuncSetAttribute(gemm_kernel<256, 2, 4, 2>,
                         cudaFuncAttributeMaxDynamicSharedMemorySize, SMEM_TOTAL);

    // odd rows (2r+1): 512x512 @ d
    gemm_kernel<512, 0, 2, 1><<<dim3(4, 256), THREADS, SMEM_TOTAL>>>(out);
    // rows 4t: 256x256 @ ss
    gemm_kernel<256, 1, 4, 0><<<dim3(2, 256), THREADS, SMEM_TOTAL>>>(out);
    // rows 4t+2: 256x256 @ sd
    gemm_kernel<256, 2, 4, 2><<<dim3(2, 256), THREADS, SMEM_TOTAL>>>(out);
}

// round 13
// speedup vs baseline: 1.2481x; 1.0805x over previous
#include <cuda_runtime.h>
#include <cuda_fp16.h>
#include <cstdint>

#define DEV_INLINE __device__ __forceinline__

static constexpr int NDIM   = 1024;
static constexpr int NBATCH = 32;

// GEMM tiling (portable mma.sync; tcgen05 rejected by compute_103 PTX target)
static constexpr int BM = 128;
static constexpr int BN = 128;
static constexpr int BK = 64;
static constexpr int STAGES = 3;
static constexpr int THREADS = 256;   // 8 warps: 2(m) x 4(n), warp tile 64x32 (proven)

static constexpr int A_STAGE_BYTES = BM * 128;              // 16 KB
static constexpr int B_STAGE_BYTES = BK * 256;              // 16 KB
static constexpr int STAGE_BYTES   = A_STAGE_BYTES + B_STAGE_BYTES;   // 32 KB
static constexpr int SMEM_TOTAL    = STAGES * STAGE_BYTES;  // 96 KB (gemm512)

// Resident-B 256-GEMM smem plan: 2 A stages (16 KB each) + full B panel (64 KB) = 96 KB
static constexpr int A2_STAGE  = 16384;
static constexpr int B_OFF     = 2 * A2_STAGE;              // 32768
static constexpr int SMEM256   = B_OFF + 65536;             // 96 KB

// Folded DCT (level 2 on even branch), B operands in INPUT layout [b][j][m]:
//   odd rows k=2r+1: Out = Codd(512x512) @ d    d[j]  = x[j]-x[1023-j]
//   rows k=4t:       Out = Cee (256x256) @ ss   ss[j] = s[j]+s[511-j]
//   rows k=4t+2:     Out = Ceo (256x256) @ sd   sd[j] = s[j]-s[511-j],  s[j]=x[j]+x[1023-j]
__device__ __half d_Codd[512 * 512];                    // [r][j] K-contig
__device__ __half d_Cee[256 * 256];
__device__ __half d_Ceo[256 * 256];
__device__ __half d_xd [(size_t)NBATCH * 512 * 1024];   // [b][j<512][m]
__device__ __half d_xss[(size_t)NBATCH * 256 * 1024];   // [b][j<256][m]
__device__ __half d_xsd[(size_t)NBATCH * 256 * 1024];

// ---------------------------------------------------------------- helpers
DEV_INLINE uint32_t smem_u32(const void* p) {
    uint32_t a;
    asm("{ .reg .u64 t; cvta.to.shared.u64 t, %1; cvt.u32.u64 %0, t; }" : "=r"(a) : "l"(p));
    return a;
}
DEV_INLINE void cp16(uint32_t saddr, const void* g) {
    asm volatile("cp.async.cg.shared.global [%0], [%1], 16;" :: "r"(saddr), "l"(g));
}
DEV_INLINE void cp_commit() { asm volatile("cp.async.commit_group;"); }
template <int N> DEV_INLINE void cp_wait() { asm volatile("cp.async.wait_group %0;" :: "n"(N)); }
DEV_INLINE uint32_t swz(uint32_t off) { return off ^ ((off >> 3) & 0x70); }

DEV_INLINE void ldsm4(uint32_t* r, uint32_t addr) {
    asm volatile("ldmatrix.sync.aligned.m8n8.x4.shared.b16 {%0,%1,%2,%3}, [%4];"
                 : "=r"(r[0]), "=r"(r[1]), "=r"(r[2]), "=r"(r[3]) : "r"(addr));
}
DEV_INLINE void ldsm4t(uint32_t* r, uint32_t addr) {
    asm volatile("ldmatrix.sync.aligned.m8n8.x4.trans.shared.b16 {%0,%1,%2,%3}, [%4];"
                 : "=r"(r[0]), "=r"(r[1]), "=r"(r[2]), "=r"(r[3]) : "r"(addr));
}
DEV_INLINE void mma16816(float* c, const uint32_t* a, const uint32_t* b) {
    asm volatile(
        "mma.sync.aligned.m16n8k16.row.col.f32.f16.f16.f32 "
        "{%0,%1,%2,%3}, {%4,%5,%6,%7}, {%8,%9}, {%0,%1,%2,%3};"
        : "+f"(c[0]), "+f"(c[1]), "+f"(c[2]), "+f"(c[3])
        : "r"(a[0]), "r"(a[1]), "r"(a[2]), "r"(a[3]), "r"(b[0]), "r"(b[1]));
}
DEV_INLINE uint32_t f2h2(float a, float b) {
    __half2 h = __floats2half2_rn(a, b);
    return *reinterpret_cast<uint32_t*>(&h);
}
DEV_INLINE float4 add4(float4 a, float4 b) { return {a.x+b.x, a.y+b.y, a.z+b.z, a.w+b.w}; }
DEV_INLINE float4 sub4(float4 a, float4 b) { return {a.x-b.x, a.y-b.y, a.z-b.z, a.w-b.w}; }
DEV_INLINE void st8h(__half* p, float4 u, float4 v) {
    uint4 o = { f2h2(u.x,u.y), f2h2(u.z,u.w), f2h2(v.x,v.y), f2h2(v.z,v.w) };
    *reinterpret_cast<uint4*>(p) = o;
}

// ---------------------------------------------------------------- kernel 1: prep (fold + matrices)
// blocks [0,4096): streaming fold.  blocks [4096,5632): DCT matrix build.
__global__ void prep_kernel(const float* __restrict__ x) {
    int blk = blockIdx.x;
    if (blk < 4096) {
        int idx = blk * 256 + threadIdx.x;          // 0 .. 1048575
        int b = idx >> 15;
        int rem = idx & 32767;
        int j = rem >> 7;                            // 0..255
        int m = (rem & 127) << 3;                    // 8 floats
        const float* xb = x + ((size_t)b << 20);
        const float4* pa = (const float4*)(xb + (size_t)j * 1024 + m);
        const float4* pb = (const float4*)(xb + (size_t)(1023 - j) * 1024 + m);
        const float4* pc = (const float4*)(xb + (size_t)(511 - j) * 1024 + m);
        const float4* pe = (const float4*)(xb + (size_t)(512 + j) * 1024 + m);
        float4 a0 = pa[0], a1 = pa[1];
        float4 b0 = pb[0], b1 = pb[1];
        float4 c0 = pc[0], c1 = pc[1];
        float4 e0 = pe[0], e1 = pe[1];
        float4 slo0 = add4(a0, b0), slo1 = add4(a1, b1);   // s[j]
        float4 shi0 = add4(c0, e0), shi1 = add4(c1, e1);   // s[511-j]
        st8h(d_xd  + ((size_t)b * 512 + j)       * 1024 + m, sub4(a0, b0), sub4(a1, b1));
        st8h(d_xd  + ((size_t)b * 512 + 511 - j) * 1024 + m, sub4(c0, e0), sub4(c1, e1));
        st8h(d_xss + ((size_t)b * 256 + j)       * 1024 + m, add4(slo0, shi0), add4(slo1, shi1));
        st8h(d_xsd + ((size_t)b * 256 + j)       * 1024 + m, sub4(slo0, shi0), sub4(slo1, shi1));
    } else {
        int idx = (blk - 4096) * 256 + threadIdx.x;  // 0 .. 393215
        int k, j;
        __half* dst;
        if (idx < 262144) {                          // Codd
            j = idx & 511; k = 2 * (idx >> 9) + 1; dst = d_Codd + idx;
        } else if (idx < 327680) {                   // Cee
            int l = idx - 262144;
            j = l & 255; k = 4 * (l >> 8); dst = d_Cee + l;
        } else {                                     // Ceo
            int l = idx - 327680;
            j = l & 255; k = 4 * (l >> 8) + 2; dst = d_Ceo + l;
        }
        int t = ((k * (2 * j + 1) + 2048) & 4095) - 2048;
        float ang = (float)t * 1.5339807878856412e-3f;   // pi/2048
        float s = (k == 0) ? 0.03125f : 0.04419417382415922f;
        *dst = __float2half(s * __cosf(ang));
    }
}

// ---------------------------------------------------------------- kernel 2: odd GEMM (K=512, proven)
DEV_INLINE void load_chunk512(int q, int stage, int tid, const __half* Asrc,
                              const __half* Bsrc, uint32_t sbase) {
    uint32_t abase = sbase + stage * STAGE_BYTES;
    uint32_t bbase = abase + A_STAGE_BYTES;
    int kc0 = q * BK;
#pragma unroll
    for (int i = 0; i < 4; i++) {
        int s = tid + i * THREADS;
        int row = s >> 3, seg = s & 7;
        cp16(abase + swz((uint32_t)(row * 128 + seg * 16)),
             (const void*)(Asrc + (size_t)row * 512 + kc0 + seg * 8));
    }
#pragma unroll
    for (int i = 0; i < 4; i++) {
        int s = tid + i * THREADS;
        int krow = s >> 4, seg = s & 15;
        cp16(bbase + (uint32_t)((seg >> 3) * 8192) +
                 swz((uint32_t)(krow * 128 + (seg & 7) * 16)),
             (const void*)(Bsrc + (size_t)(kc0 + krow) * 1024 + seg * 8));
    }
}

__global__ void __launch_bounds__(THREADS, 2) gemm512_kernel(float* __restrict__ out) {
    constexpr int NCH = 8;
    extern __shared__ char smem[];
    uint32_t sbase = smem_u32(smem);
    int tid = threadIdx.x;
    int lane = tid & 31, wid = tid >> 5;
    int warp_m = wid & 1;
    int warp_n = wid >> 1;

    int k0 = blockIdx.x * BM;
    int b  = blockIdx.y >> 3;
    int m0 = (blockIdx.y & 7) * BN;
    const __half* Apanel = d_Codd + (size_t)k0 * 512;
    const __half* Bpanel = d_xd + (size_t)b * 512 * 1024 + m0;

    float acc[4][4][4] = {};

    int a_row = warp_m * 64 + (lane & 7) + (((lane >> 3) & 1) << 3);
    int a_kx  = (lane >> 4) << 3;
    int b_jr  = (lane & 7) + (((lane >> 3) & 1) << 3);
    int b_ns  = (lane >> 4) << 3;

#pragma unroll
    for (int s = 0; s < STAGES - 1; s++) {
        load_chunk512(s, s, tid, Apanel, Bpanel, sbase); cp_commit();
    }

    for (int c = 0; c < NCH; c++) {
        int q = c + STAGES - 1;
        if (q < NCH) load_chunk512(q, q % STAGES, tid, Apanel, Bpanel, sbase);
        cp_commit();
        cp_wait<STAGES - 1>();
        __syncthreads();

        uint32_t abase = sbase + (c % STAGES) * STAGE_BYTES;
        uint32_t bbase = abase + A_STAGE_BYTES;
#pragma unroll
        for (int ks = 0; ks < BK / 16; ks++) {
            uint32_t af[4][4];
#pragma unroll
            for (int mi = 0; mi < 4; mi++)
                ldsm4(af[mi], abase + swz((uint32_t)((a_row + mi * 16) * 128 +
                                                     (ks * 16 + a_kx) * 2)));
            uint32_t bf[4][2];
#pragma unroll
            for (int g = 0; g < 2; g++) {
                int nb = warp_n * 32 + g * 16 + b_ns;
                uint32_t r[4];
                ldsm4t(r, bbase + (uint32_t)(((nb >> 6) & 1) * 8192) +
                          swz((uint32_t)((ks * 16 + b_jr) * 128 + (nb & 63) * 2)));
                bf[2 * g + 0][0] = r[0]; bf[2 * g + 0][1] = r[1];
                bf[2 * g + 1][0] = r[2]; bf[2 * g + 1][1] = r[3];
            }
#pragma unroll
            for (int mi = 0; mi < 4; mi++)
#pragma unroll
                for (int ni = 0; ni < 4; ni++)
                    mma16816(acc[mi][ni], af[mi], bf[ni]);
        }
        __syncthreads();
    }

    // epilogue: smem staging -> float4 stores, output rows 2*(k0+rr)+1
    float* stg = (float*)smem;
    int gr = lane >> 2, cl = (lane & 3) * 2;
#pragma unroll
    for (int mi = 0; mi < 4; mi++)
#pragma unroll
        for (int ni = 0; ni < 4; ni++) {
            int r0 = warp_m * 64 + mi * 16 + gr;
            int col = warp_n * 32 + ni * 8 + cl;
            stg[r0 * 132 + col]           = acc[mi][ni][0];
            stg[r0 * 132 + col + 1]       = acc[mi][ni][1];
            stg[(r0 + 8) * 132 + col]     = acc[mi][ni][2];
            stg[(r0 + 8) * 132 + col + 1] = acc[mi][ni][3];
        }
    __syncthreads();

    size_t ob = ((size_t)b << 20) + (size_t)(2 * k0 + 1) * 1024 + m0;
#pragma unroll
    for (int i = 0; i < 16; i++) {
        int idx = i * THREADS + tid;
        int row = idx >> 5;
        int c4 = (idx & 31) * 4;
        float4 v = *(const float4*)(stg + row * 132 + c4);
        *(float4*)(out + ob + (size_t)row * 2048 + c4) = v;
    }
}

// ---------------------------------------------------------------- kernel 3: resident-B 256 GEMM
// One CTA owns one n-tile of one segment (ee or eo): loads full B panel (256x128)
// into smem once, streams 8 A-chunks (2 k-tiles x 4) through a 2-stage pipeline,
// direct float2 epilogue per k-tile (B stays resident).
DEV_INLINE void load_a256(int g, int tid, const __half* Amat, uint32_t sbase) {
    uint32_t abase = sbase + (g & 1) * A2_STAGE;
    int kt = g >> 2, kc0 = (g & 3) * 64;
    const __half* Ap = Amat + (size_t)(kt * 128) * 256 + kc0;
#pragma unroll
    for (int i = 0; i < 4; i++) {
        int s = tid + i * 256;
        int row = s >> 3, seg = s & 7;
        cp16(abase + swz((uint32_t)(row * 128 + seg * 16)),
             (const void*)(Ap + (size_t)row * 256 + seg * 8));
    }
}

__global__ void __launch_bounds__(256, 2) gemm256_kernel(float* __restrict__ out) {
    extern __shared__ char smem[];
    uint32_t sbase = smem_u32(smem);
    int tid = threadIdx.x;
    int lane = tid & 31, wid = tid >> 5;
    int warp_m = wid & 1;
    int warp_n = wid >> 1;

    int blk = blockIdx.x;
    int seg = blk >> 8;                 // 0: ee (rows 4t), 1: eo (rows 4t+2)
    int nt  = blk & 255;
    int b   = nt >> 3;
    int m0  = (nt & 7) * BN;
    const __half* Amat = seg ? d_Ceo : d_Cee;
    const __half* Bmat = seg ? d_xsd : d_xss;
    int rowoff = seg ? 2 : 0;
    const __half* Bpanel = Bmat + (size_t)b * 256 * 1024 + m0;

    // B fill: 256 k-rows x 128 m fp16 = 64KB, two 64-col halves of 32KB
#pragma unroll
    for (int i = 0; i < 16; i++) {
        int s = tid + i * 256;
        int krow = s >> 4, sg = s & 15;
        cp16(sbase + B_OFF + (uint32_t)((sg >> 3) * 32768) +
                 swz((uint32_t)(krow * 128 + (sg & 7) * 16)),
             (const void*)(Bpanel + (size_t)krow * 1024 + sg * 8));
    }
    cp_commit();
    load_a256(0, tid, Amat, sbase); cp_commit();
    load_a256(1, tid, Amat, sbase); cp_commit();

    float acc[4][4][4] = {};

    int a_row = warp_m * 64 + (lane & 7) + (((lane >> 3) & 1) << 3);
    int a_kx  = (lane >> 4) << 3;
    int b_jr  = (lane & 7) + (((lane >> 3) & 1) << 3);
    int b_ns  = (lane >> 4) << 3;
    int gr = lane >> 2, cl = (lane & 3) * 2;

    for (int g = 0; g < 8; g++) {
        cp_wait<1>();                 // B + A-chunks..g resident
        __syncthreads();

        uint32_t abase = sbase + (g & 1) * A2_STAGE;
        int kc0 = (g & 3) * 64;
#pragma unroll
        for (int ks = 0; ks < 4; ks++) {
            uint32_t af[4][4];
#pragma unroll
            for (int mi = 0; mi < 4; mi++)
                ldsm4(af[mi], abase + swz((uint32_t)((a_row + mi * 16) * 128 +
                                                     (ks * 16 + a_kx) * 2)));
            uint32_t bf[4][2];
#pragma unroll
            for (int h = 0; h < 2; h++) {
                int nb = warp_n * 32 + h * 16 + b_ns;
                uint32_t r[4];
                ldsm4t(r, sbase + B_OFF + (uint32_t)(((nb >> 6) & 1) * 32768) +
                          swz((uint32_t)((kc0 + ks * 16 + b_jr) * 128 + (nb & 63) * 2)));
                bf[2 * h + 0][0] = r[0]; bf[2 * h + 0][1] = r[1];
                bf[2 * h + 1][0] = r[2]; bf[2 * h + 1][1] = r[3];
            }
#pragma unroll
            for (int mi = 0; mi < 4; mi++)
#pragma unroll
                for (int ni = 0; ni < 4; ni++)
                    mma16816(acc[mi][ni], af[mi], bf[ni]);
        }

        if ((g & 3) == 3) {
            // direct epilogue for k-tile kt = g>>2: out rows 4*(kt*128+r)+rowoff
            int kt = g >> 2;
            size_t obase = ((size_t)b << 20) + (size_t)rowoff * 1024 + m0;
#pragma unroll
            for (int mi = 0; mi < 4; mi++)
#pragma unroll
                for (int ni = 0; ni < 4; ni++) {
                    int r0 = kt * 128 + warp_m * 64 + mi * 16 + gr;
                    int col = warp_n * 32 + ni * 8 + cl;
                    float2 v0 = { acc[mi][ni][0], acc[mi][ni][1] };
                    float2 v1 = { acc[mi][ni][2], acc[mi][ni][3] };
                    *(float2*)(out + obase + (size_t)(4 * r0) * 1024 + col)       = v0;
                    *(float2*)(out + obase + (size_t)(4 * (r0 + 8)) * 1024 + col) = v1;
                    acc[mi][ni][0] = acc[mi][ni][1] = 0.0f;
                    acc[mi][ni][2] = acc[mi][ni][3] = 0.0f;
                }
        }

        __syncthreads();              // stage (g&1) fully consumed before overwrite
        if (g + 2 < 8) load_a256(g + 2, tid, Amat, sbase);
        cp_commit();                  // always commit (possibly empty group)
    }
}

// ---------------------------------------------------------------- launch
extern "C" void kernel_launch(void* const* d_in, const int* in_sizes, int n_in,
                              void* d_out, int out_size) {
    (void)in_sizes; (void)n_in; (void)out_size;
    const float* x = (const float*)d_in[0];
    float* out = (float*)d_out;

    prep_kernel<<<5632, 256>>>(x);

    cudaFuncSetAttribute(gemm512_kernel,
                         cudaFuncAttributeMaxDynamicSharedMemorySize, SMEM_TOTAL);
    cudaFuncSetAttribute(gemm256_kernel,
                         cudaFuncAttributeMaxDynamicSharedMemorySize, SMEM256);

    // odd rows (2r+1): 512x512 @ d
    gemm512_kernel<<<dim3(4, 256), THREADS, SMEM_TOTAL>>>(out);
    // rows 4t (ee) and 4t+2 (eo): resident-B, both segments in one launch
    gemm256_kernel<<<512, 256, SMEM256>>>(out);
}

// round 15
// speedup vs baseline: 1.3038x; 1.0446x over previous
#include <cuda_runtime.h>
#include <cuda_fp16.h>
#include <cstdint>

#define DEV_INLINE __device__ __forceinline__

static constexpr int NDIM   = 1024;
static constexpr int NBATCH = 32;

// GEMM tiling (portable mma.sync; tcgen05 rejected by compute_103 PTX target)
static constexpr int BM = 128;
static constexpr int BN = 128;
static constexpr int BK = 64;
static constexpr int STAGES = 3;
static constexpr int THREADS = 256;   // 8 warps: 2(m) x 4(n), warp tile 64x32 (proven)

static constexpr int A_STAGE_BYTES = BM * 128;              // 16 KB
static constexpr int B_STAGE_BYTES = BK * 256;              // 16 KB
static constexpr int STAGE_BYTES   = A_STAGE_BYTES + B_STAGE_BYTES;   // 32 KB
static constexpr int SMEM_TOTAL    = STAGES * STAGE_BYTES;  // 96 KB

// Resident-B 256-path smem plan: 2 A stages (16 KB) + full B panel (64 KB) = 96 KB
static constexpr int A2_STAGE  = 16384;
static constexpr int B_OFF     = 2 * A2_STAGE;              // 32768

// Folded DCT (level 2 on even branch), B operands in INPUT layout [b][j][m]:
//   odd rows k=2r+1: Out = Codd(512x512) @ d    d[j]  = x[j]-x[1023-j]
//   rows k=4t:       Out = Cee (256x256) @ ss   ss[j] = s[j]+s[511-j]
//   rows k=4t+2:     Out = Ceo (256x256) @ sd   sd[j] = s[j]-s[511-j],  s[j]=x[j]+x[1023-j]
__device__ __half d_Codd[512 * 512];                    // [r][j] K-contig
__device__ __half d_Cee[256 * 256];
__device__ __half d_Ceo[256 * 256];
__device__ __half d_xd [(size_t)NBATCH * 512 * 1024];   // [b][j<512][m]
__device__ __half d_xss[(size_t)NBATCH * 256 * 1024];   // [b][j<256][m]
__device__ __half d_xsd[(size_t)NBATCH * 256 * 1024];

// ---------------------------------------------------------------- helpers
DEV_INLINE uint32_t smem_u32(const void* p) {
    uint32_t a;
    asm("{ .reg .u64 t; cvta.to.shared.u64 t, %1; cvt.u32.u64 %0, t; }" : "=r"(a) : "l"(p));
    return a;
}
DEV_INLINE void cp16(uint32_t saddr, const void* g) {
    asm volatile("cp.async.cg.shared.global [%0], [%1], 16;" :: "r"(saddr), "l"(g));
}
DEV_INLINE void cp_commit() { asm volatile("cp.async.commit_group;"); }
template <int N> DEV_INLINE void cp_wait() { asm volatile("cp.async.wait_group %0;" :: "n"(N)); }
DEV_INLINE uint32_t swz(uint32_t off) { return off ^ ((off >> 3) & 0x70); }

DEV_INLINE void ldsm4(uint32_t* r, uint32_t addr) {
    asm volatile("ldmatrix.sync.aligned.m8n8.x4.shared.b16 {%0,%1,%2,%3}, [%4];"
                 : "=r"(r[0]), "=r"(r[1]), "=r"(r[2]), "=r"(r[3]) : "r"(addr));
}
DEV_INLINE void ldsm4t(uint32_t* r, uint32_t addr) {
    asm volatile("ldmatrix.sync.aligned.m8n8.x4.trans.shared.b16 {%0,%1,%2,%3}, [%4];"
                 : "=r"(r[0]), "=r"(r[1]), "=r"(r[2]), "=r"(r[3]) : "r"(addr));
}
DEV_INLINE void mma16816(float* c, const uint32_t* a, const uint32_t* b) {
    asm volatile(
        "mma.sync.aligned.m16n8k16.row.col.f32.f16.f16.f32 "
        "{%0,%1,%2,%3}, {%4,%5,%6,%7}, {%8,%9}, {%0,%1,%2,%3};"
        : "+f"(c[0]), "+f"(c[1]), "+f"(c[2]), "+f"(c[3])
        : "r"(a[0]), "r"(a[1]), "r"(a[2]), "r"(a[3]), "r"(b[0]), "r"(b[1]));
}
DEV_INLINE uint32_t f2h2(float a, float b) {
    __half2 h = __floats2half2_rn(a, b);
    return *reinterpret_cast<uint32_t*>(&h);
}
DEV_INLINE float4 add4(float4 a, float4 b) { return {a.x+b.x, a.y+b.y, a.z+b.z, a.w+b.w}; }
DEV_INLINE float4 sub4(float4 a, float4 b) { return {a.x-b.x, a.y-b.y, a.z-b.z, a.w-b.w}; }
DEV_INLINE void st8h(__half* p, float4 u, float4 v) {
    uint4 o = { f2h2(u.x,u.y), f2h2(u.z,u.w), f2h2(v.x,v.y), f2h2(v.z,v.w) };
    *reinterpret_cast<uint4*>(p) = o;
}

// ---------------------------------------------------------------- kernel 1: prep (fold + matrices)
// blocks [0,4096): streaming fold (HBM-roofline).  blocks [4096,5632): matrix build.
__global__ void prep_kernel(const float* __restrict__ x) {
    int blk = blockIdx.x;
    if (blk < 4096) {
        int idx = blk * 256 + threadIdx.x;          // 0 .. 1048575
        int b = idx >> 15;
        int rem = idx & 32767;
        int j = rem >> 7;                            // 0..255
        int m = (rem & 127) << 3;                    // 8 floats
        const float* xb = x + ((size_t)b << 20);
        const float4* pa = (const float4*)(xb + (size_t)j * 1024 + m);
        const float4* pb = (const float4*)(xb + (size_t)(1023 - j) * 1024 + m);
        const float4* pc = (const float4*)(xb + (size_t)(511 - j) * 1024 + m);
        const float4* pe = (const float4*)(xb + (size_t)(512 + j) * 1024 + m);
        float4 a0 = pa[0], a1 = pa[1];
        float4 b0 = pb[0], b1 = pb[1];
        float4 c0 = pc[0], c1 = pc[1];
        float4 e0 = pe[0], e1 = pe[1];
        float4 slo0 = add4(a0, b0), slo1 = add4(a1, b1);   // s[j]
        float4 shi0 = add4(c0, e0), shi1 = add4(c1, e1);   // s[511-j]
        st8h(d_xd  + ((size_t)b * 512 + j)       * 1024 + m, sub4(a0, b0), sub4(a1, b1));
        st8h(d_xd  + ((size_t)b * 512 + 511 - j) * 1024 + m, sub4(c0, e0), sub4(c1, e1));
        st8h(d_xss + ((size_t)b * 256 + j)       * 1024 + m, add4(slo0, shi0), add4(slo1, shi1));
        st8h(d_xsd + ((size_t)b * 256 + j)       * 1024 + m, sub4(slo0, shi0), sub4(slo1, shi1));
    } else {
        int idx = (blk - 4096) * 256 + threadIdx.x;  // 0 .. 393215
        int k, j;
        __half* dst;
        if (idx < 262144) {                          // Codd
            j = idx & 511; k = 2 * (idx >> 9) + 1; dst = d_Codd + idx;
        } else if (idx < 327680) {                   // Cee
            int l = idx - 262144;
            j = l & 255; k = 4 * (l >> 8); dst = d_Cee + l;
        } else {                                     // Ceo
            int l = idx - 327680;
            j = l & 255; k = 4 * (l >> 8) + 2; dst = d_Ceo + l;
        }
        int t = ((k * (2 * j + 1) + 2048) & 4095) - 2048;
        float ang = (float)t * 1.5339807878856412e-3f;   // pi/2048
        float s = (k == 0) ? 0.03125f : 0.04419417382415922f;
        *dst = __float2half(s * __cosf(ang));
    }
}

// ---------------------------------------------------------------- GEMM bodies
// 512-path: 3-stage pipelined K=512 (proven)
DEV_INLINE void load_chunk512(int q, int stage, int tid, const __half* Asrc,
                              const __half* Bsrc, uint32_t sbase) {
    uint32_t abase = sbase + stage * STAGE_BYTES;
    uint32_t bbase = abase + A_STAGE_BYTES;
    int kc0 = q * BK;
#pragma unroll
    for (int i = 0; i < 4; i++) {
        int s = tid + i * THREADS;
        int row = s >> 3, seg = s & 7;
        cp16(abase + swz((uint32_t)(row * 128 + seg * 16)),
             (const void*)(Asrc + (size_t)row * 512 + kc0 + seg * 8));
    }
#pragma unroll
    for (int i = 0; i < 4; i++) {
        int s = tid + i * THREADS;
        int krow = s >> 4, seg = s & 15;
        cp16(bbase + (uint32_t)((seg >> 3) * 8192) +
                 swz((uint32_t)(krow * 128 + (seg & 7) * 16)),
             (const void*)(Bsrc + (size_t)(kc0 + krow) * 1024 + seg * 8));
    }
}

DEV_INLINE void gemm512_body(float* __restrict__ out, int blk, uint32_t sbase, char* smem) {
    constexpr int NCH = 8;
    int tid = threadIdx.x;
    int lane = tid & 31, wid = tid >> 5;
    int warp_m = wid & 1;
    int warp_n = wid >> 1;

    int k0 = (blk & 3) * BM;
    int nt = blk >> 2;
    int b  = nt >> 3;
    int m0 = (nt & 7) * BN;
    const __half* Apanel = d_Codd + (size_t)k0 * 512;
    const __half* Bpanel = d_xd + (size_t)b * 512 * 1024 + m0;

    float acc[4][4][4] = {};

    int a_row = warp_m * 64 + (lane & 7) + (((lane >> 3) & 1) << 3);
    int a_kx  = (lane >> 4) << 3;
    int b_jr  = (lane & 7) + (((lane >> 3) & 1) << 3);
    int b_ns  = (lane >> 4) << 3;

#pragma unroll
    for (int s = 0; s < STAGES - 1; s++) {
        load_chunk512(s, s, tid, Apanel, Bpanel, sbase); cp_commit();
    }

    for (int c = 0; c < NCH; c++) {
        int q = c + STAGES - 1;
        if (q < NCH) load_chunk512(q, q % STAGES, tid, Apanel, Bpanel, sbase);
        cp_commit();
        cp_wait<STAGES - 1>();
        __syncthreads();

        uint32_t abase = sbase + (c % STAGES) * STAGE_BYTES;
        uint32_t bbase = abase + A_STAGE_BYTES;
#pragma unroll
        for (int ks = 0; ks < BK / 16; ks++) {
            uint32_t af[4][4];
#pragma unroll
            for (int mi = 0; mi < 4; mi++)
                ldsm4(af[mi], abase + swz((uint32_t)((a_row + mi * 16) * 128 +
                                                     (ks * 16 + a_kx) * 2)));
            uint32_t bf[4][2];
#pragma unroll
            for (int g = 0; g < 2; g++) {
                int nb = warp_n * 32 + g * 16 + b_ns;
                uint32_t r[4];
                ldsm4t(r, bbase + (uint32_t)(((nb >> 6) & 1) * 8192) +
                          swz((uint32_t)((ks * 16 + b_jr) * 128 + (nb & 63) * 2)));
                bf[2 * g + 0][0] = r[0]; bf[2 * g + 0][1] = r[1];
                bf[2 * g + 1][0] = r[2]; bf[2 * g + 1][1] = r[3];
            }
#pragma unroll
            for (int mi = 0; mi < 4; mi++)
#pragma unroll
                for (int ni = 0; ni < 4; ni++)
                    mma16816(acc[mi][ni], af[mi], bf[ni]);
        }
        __syncthreads();
    }

    // epilogue: smem staging -> float4 stores, output rows 2*(k0+rr)+1
    float* stg = (float*)smem;
    int gr = lane >> 2, cl = (lane & 3) * 2;
#pragma unroll
    for (int mi = 0; mi < 4; mi++)
#pragma unroll
        for (int ni = 0; ni < 4; ni++) {
            int r0 = warp_m * 64 + mi * 16 + gr;
            int col = warp_n * 32 + ni * 8 + cl;
            stg[r0 * 132 + col]           = acc[mi][ni][0];
            stg[r0 * 132 + col + 1]       = acc[mi][ni][1];
            stg[(r0 + 8) * 132 + col]     = acc[mi][ni][2];
            stg[(r0 + 8) * 132 + col + 1] = acc[mi][ni][3];
        }
    __syncthreads();

    size_t ob = ((size_t)b << 20) + (size_t)(2 * k0 + 1) * 1024 + m0;
#pragma unroll
    for (int i = 0; i < 16; i++) {
        int idx = i * THREADS + tid;
        int row = idx >> 5;
        int c4 = (idx & 31) * 4;
        float4 v = *(const float4*)(stg + row * 132 + c4);
        *(float4*)(out + ob + (size_t)row * 2048 + c4) = v;
    }
}

// 256-path: resident-B (64 KB panel loaded once), 2-stage A pipeline, direct epilogue
DEV_INLINE void load_a256(int g, int tid, const __half* Amat, uint32_t sbase) {
    uint32_t abase = sbase + (g & 1) * A2_STAGE;
    int kt = g >> 2, kc0 = (g & 3) * 64;
    const __half* Ap = Amat + (size_t)(kt * 128) * 256 + kc0;
#pragma unroll
    for (int i = 0; i < 4; i++) {
        int s = tid + i * 256;
        int row = s >> 3, seg = s & 7;
        cp16(abase + swz((uint32_t)(row * 128 + seg * 16)),
             (const void*)(Ap + (size_t)row * 256 + seg * 8));
    }
}

DEV_INLINE void gemm256_body(float* __restrict__ out, int blk, uint32_t sbase) {
    int tid = threadIdx.x;
    int lane = tid & 31, wid = tid >> 5;
    int warp_m = wid & 1;
    int warp_n = wid >> 1;

    int seg = blk >> 8;                 // 0: ee (rows 4t), 1: eo (rows 4t+2)
    int nt  = blk & 255;
    int b   = nt >> 3;
    int m0  = (nt & 7) * BN;
    const __half* Amat = seg ? d_Ceo : d_Cee;
    const __half* Bmat = seg ? d_xsd : d_xss;
    int rowoff = seg ? 2 : 0;
    const __half* Bpanel = Bmat + (size_t)b * 256 * 1024 + m0;

    // B fill: 256 k-rows x 128 m fp16 = 64KB, two 64-col halves of 32KB
#pragma unroll
    for (int i = 0; i < 16; i++) {
        int s = tid + i * 256;
        int krow = s >> 4, sg = s & 15;
        cp16(sbase + B_OFF + (uint32_t)((sg >> 3) * 32768) +
                 swz((uint32_t)(krow * 128 + (sg & 7) * 16)),
             (const void*)(Bpanel + (size_t)krow * 1024 + sg * 8));
    }
    cp_commit();
    load_a256(0, tid, Amat, sbase); cp_commit();
    load_a256(1, tid, Amat, sbase); cp_commit();

    float acc[4][4][4] = {};

    int a_row = warp_m * 64 + (lane & 7) + (((lane >> 3) & 1) << 3);
    int a_kx  = (lane >> 4) << 3;
    int b_jr  = (lane & 7) + (((lane >> 3) & 1) << 3);
    int b_ns  = (lane >> 4) << 3;
    int gr = lane >> 2, cl = (lane & 3) * 2;

    for (int g = 0; g < 8; g++) {
        cp_wait<1>();                 // B + A-chunks..g resident
        __syncthreads();

        uint32_t abase = sbase + (g & 1) * A2_STAGE;
        int kc0 = (g & 3) * 64;
#pragma unroll
        for (int ks = 0; ks < 4; ks++) {
            uint32_t af[4][4];
#pragma unroll
            for (int mi = 0; mi < 4; mi++)
                ldsm4(af[mi], abase + swz((uint32_t)((a_row + mi * 16) * 128 +
                                                     (ks * 16 + a_kx) * 2)));
            uint32_t bf[4][2];
#pragma unroll
            for (int h = 0; h < 2; h++) {
                int nb = warp_n * 32 + h * 16 + b_ns;
                uint32_t r[4];
                ldsm4t(r, sbase + B_OFF + (uint32_t)(((nb >> 6) & 1) * 32768) +
                          swz((uint32_t)((kc0 + ks * 16 + b_jr) * 128 + (nb & 63) * 2)));
                bf[2 * h + 0][0] = r[0]; bf[2 * h + 0][1] = r[1];
                bf[2 * h + 1][0] = r[2]; bf[2 * h + 1][1] = r[3];
            }
#pragma unroll
            for (int mi = 0; mi < 4; mi++)
#pragma unroll
                for (int ni = 0; ni < 4; ni++)
                    mma16816(acc[mi][ni], af[mi], bf[ni]);
        }

        if ((g & 3) == 3) {
            int kt = g >> 2;
            size_t obase = ((size_t)b << 20) + (size_t)rowoff * 1024 + m0;
#pragma unroll
            for (int mi = 0; mi < 4; mi++)
#pragma unroll
                for (int ni = 0; ni < 4; ni++) {
                    int r0 = kt * 128 + warp_m * 64 + mi * 16 + gr;
                    int col = warp_n * 32 + ni * 8 + cl;
                    float2 v0 = { acc[mi][ni][0], acc[mi][ni][1] };
                    float2 v1 = { acc[mi][ni][2], acc[mi][ni][3] };
                    *(float2*)(out + obase + (size_t)(4 * r0) * 1024 + col)       = v0;
                    *(float2*)(out + obase + (size_t)(4 * (r0 + 8)) * 1024 + col) = v1;
                    acc[mi][ni][0] = acc[mi][ni][1] = 0.0f;
                    acc[mi][ni][2] = acc[mi][ni][3] = 0.0f;
                }
        }

        __syncthreads();              // stage (g&1) fully consumed before overwrite
        if (g + 2 < 8) load_a256(g + 2, tid, Amat, sbase);
        cp_commit();                  // always commit (possibly empty group)
    }
}

// One launch for all GEMM work: 1024 (odd/K=512) + 512 (ee+eo/K=256, resident-B).
// Heavy 512-path CTAs first; 256-path fills the final waves.
__global__ void __launch_bounds__(THREADS, 2) fused_gemm_kernel(float* __restrict__ out) {
    extern __shared__ char smem[];
    uint32_t sbase = smem_u32(smem);
    int blk = blockIdx.x;
    if (blk < 1024) gemm512_body(out, blk, sbase, smem);
    else            gemm256_body(out, blk - 1024, sbase);
}

// ---------------------------------------------------------------- launch
extern "C" void kernel_launch(void* const* d_in, const int* in_sizes, int n_in,
                              void* d_out, int out_size) {
    (void)in_sizes; (void)n_in; (void)out_size;
    const float* x = (const float*)d_in[0];
    float* out = (float*)d_out;

    prep_kernel<<<5632, 256>>>(x);

    cudaFuncSetAttribute(fused_gemm_kernel,
                         cudaFuncAttributeMaxDynamicSharedMemorySize, SMEM_TOTAL);
    fused_gemm_kernel<<<1536, THREADS, SMEM_TOTAL>>>(out);
}